// round 1
// baseline (speedup 1.0000x reference)
#include <cuda_runtime.h>
#include <cstdint>

#define N_ATOMS 50000
#define M_NBR   12
#define A_FEA   128
#define NBR_FEA 64
#define C_OUT   256
#define N_ROWS  (N_ATOMS * M_NBR)
#define BN_EPS  1e-5f

// ---------------- scratch (device globals; no allocation) ----------------
__device__ float g_P[(size_t)N_ATOMS * 512];          // [i][0:256)=atom@W1, [256:512)=atom@W2  (102.4 MB)
__device__ float g_gated[(size_t)N_ROWS * 256];       // pre-BN gated features                  (614.4 MB)
__device__ float g_nbrsum[(size_t)N_ATOMS * 128];     // summed gated neighbor features         (25.6 MB)
__device__ float g_stats1[513];                       // S[256], SS[256], cnt
__device__ float g_stats2[256];                       // S2[128], SS2[128]

// ---------------- f32x2 helpers (Blackwell packed fp32: 2x FFMA rate) ----
__device__ __forceinline__ uint64_t pack2(float lo, float hi) {
    uint64_t r;
    asm("mov.b64 %0, {%1, %2};" : "=l"(r) : "f"(lo), "f"(hi));
    return r;
}
__device__ __forceinline__ void fma2(uint64_t& d, uint64_t a, uint64_t b) {
    asm("fma.rn.f32x2 %0, %1, %2, %0;" : "+l"(d) : "l"(a), "l"(b));
}
__device__ __forceinline__ float lo32(uint64_t v) { return __uint_as_float((unsigned)(v & 0xffffffffu)); }
__device__ __forceinline__ float hi32(uint64_t v) { return __uint_as_float((unsigned)(v >> 32)); }

__device__ __forceinline__ float sigmoidf_(float x) {
    float z = expf(-fabsf(x));
    float t = 1.f / (1.f + z);
    return (x >= 0.f) ? t : z * t;
}
__device__ __forceinline__ float softplusf_(float x) {
    return fmaxf(x, 0.f) + log1pf(expf(-fabsf(x)));
}

// ---------------- kernel 0: zero stats --------------------------------
__global__ void zero_stats_kernel() {
    int t = threadIdx.x;
    if (t < 513) g_stats1[t] = 0.f;
    if (t < 256) g_stats2[t] = 0.f;
}

// ---------------- kernel A: P = atom @ [W1 | W2]  (50000x128 @ 128x512) ----
// Tile: 32 rows x 512 cols per block, 256 threads.
// Thread (cx = tid&63 -> 8 cols, ry = tid>>6 -> 8 rows as 4 f32x2 pairs).
__global__ void __launch_bounds__(256, 2) gemmA_kernel(
    const float* __restrict__ atom, const float* __restrict__ W)
{
    __shared__ float s_a[128 * 32];   // [k][r] transposed; adjacent rows = f32x2 pair

    const int tid  = threadIdx.x;
    const int row0 = blockIdx.x * 32;

    for (int t = tid; t < 1024; t += 256) {     // 32 rows x 32 float4 chunks
        int r  = t & 31;
        int kq = t >> 5;
        float4 v = make_float4(0.f, 0.f, 0.f, 0.f);
        int gr = row0 + r;
        if (gr < N_ATOMS) v = *(const float4*)(atom + (size_t)gr * 128 + kq * 4);
        s_a[(kq * 4 + 0) * 32 + r] = v.x;
        s_a[(kq * 4 + 1) * 32 + r] = v.y;
        s_a[(kq * 4 + 2) * 32 + r] = v.z;
        s_a[(kq * 4 + 3) * 32 + r] = v.w;
    }
    __syncthreads();

    const int cx = tid & 63;
    const int ry = tid >> 6;
    const int c0 = cx * 8;                       // 0..504 (global col in [W1|W2] space)
    const float* Wb = W + ((c0 < 256) ? 0 : 128 * 256) + (c0 & 255);

    uint64_t acc[4][8];
    #pragma unroll
    for (int i = 0; i < 4; i++)
        #pragma unroll
        for (int j = 0; j < 8; j++) acc[i][j] = 0ull;

    #pragma unroll 4
    for (int k = 0; k < 128; k++) {
        const float* sa = s_a + k * 32 + ry * 8;
        ulonglong2 a01 = *(const ulonglong2*)(sa);       // pairs (r0,r0+1),(r0+2,r0+3)
        ulonglong2 a23 = *(const ulonglong2*)(sa + 4);
        uint64_t ap[4] = { a01.x, a01.y, a23.x, a23.y };
        float4 w0 = *(const float4*)(Wb + k * 256);
        float4 w1 = *(const float4*)(Wb + k * 256 + 4);
        uint64_t wp[8] = { pack2(w0.x, w0.x), pack2(w0.y, w0.y), pack2(w0.z, w0.z), pack2(w0.w, w0.w),
                           pack2(w1.x, w1.x), pack2(w1.y, w1.y), pack2(w1.z, w1.z), pack2(w1.w, w1.w) };
        #pragma unroll
        for (int rp = 0; rp < 4; rp++)
            #pragma unroll
            for (int q = 0; q < 8; q++)
                fma2(acc[rp][q], ap[rp], wp[q]);
    }

    #pragma unroll
    for (int rp = 0; rp < 4; rp++) {
        int r_lo = row0 + ry * 8 + rp * 2;
        if (r_lo < N_ATOMS) {
            float4 v0, v1;
            v0.x = lo32(acc[rp][0]); v0.y = lo32(acc[rp][1]); v0.z = lo32(acc[rp][2]); v0.w = lo32(acc[rp][3]);
            v1.x = lo32(acc[rp][4]); v1.y = lo32(acc[rp][5]); v1.z = lo32(acc[rp][6]); v1.w = lo32(acc[rp][7]);
            *(float4*)(g_P + (size_t)r_lo * 512 + c0)     = v0;
            *(float4*)(g_P + (size_t)r_lo * 512 + c0 + 4) = v1;
        }
        int r_hi = r_lo + 1;
        if (r_hi < N_ATOMS) {
            float4 v0, v1;
            v0.x = hi32(acc[rp][0]); v0.y = hi32(acc[rp][1]); v0.z = hi32(acc[rp][2]); v0.w = hi32(acc[rp][3]);
            v1.x = hi32(acc[rp][4]); v1.y = hi32(acc[rp][5]); v1.z = hi32(acc[rp][6]); v1.w = hi32(acc[rp][7]);
            *(float4*)(g_P + (size_t)r_hi * 512 + c0)     = v0;
            *(float4*)(g_P + (size_t)r_hi * 512 + c0 + 4) = v1;
        }
    }
}

// ---------------- kernel B: gated = nbr@W3 + P1[i] + P2[idx] + b, + BN1 stats ----
// 4 atoms (48 rows) per block, 256 threads = one output column each.
__global__ void __launch_bounds__(256, 2) kernelB(
    const float* __restrict__ nbr, const int* __restrict__ idx,
    const float* __restrict__ mask, const float* __restrict__ W,
    const float* __restrict__ bias)
{
    __shared__ float s_v[64 * 48];   // [k][r] transposed; adjacent rows paired
    __shared__ int   s_idx[48];
    __shared__ float s_m[48];

    const int tid   = threadIdx.x;
    const int atom0 = blockIdx.x * 4;
    const int r0    = atom0 * 12;

    for (int t = tid; t < 48 * 16; t += 256) {   // 48 rows x 16 float4 chunks
        int r  = t % 48;
        int kq = t / 48;
        float4 v = *(const float4*)(nbr + (size_t)(r0 + r) * 64 + kq * 4);
        s_v[(kq * 4 + 0) * 48 + r] = v.x;
        s_v[(kq * 4 + 1) * 48 + r] = v.y;
        s_v[(kq * 4 + 2) * 48 + r] = v.z;
        s_v[(kq * 4 + 3) * 48 + r] = v.w;
    }
    if (tid < 48) { s_idx[tid] = idx[r0 + tid]; s_m[tid] = mask[r0 + tid]; }
    __syncthreads();

    const int c = tid;                               // output column 0..255
    const float* W3c = W + 256 * 256 + c;            // W3[k][c] at W3c[k*256], L1-resident (64KB)

    uint64_t acc[24];
    #pragma unroll
    for (int i = 0; i < 24; i++) acc[i] = 0ull;

    #pragma unroll 4
    for (int k = 0; k < 64; k++) {
        float w = __ldg(W3c + k * 256);
        uint64_t wp = pack2(w, w);
        const ulonglong2* vp = (const ulonglong2*)(s_v + k * 48);
        #pragma unroll
        for (int rq = 0; rq < 12; rq++) {
            ulonglong2 v2 = vp[rq];
            fma2(acc[2 * rq],     v2.x, wp);
            fma2(acc[2 * rq + 1], v2.y, wp);
        }
    }

    const float bc = bias[c];
    float sloc = 0.f, ssloc = 0.f;
    #pragma unroll 4
    for (int rr = 0; rr < 48; rr++) {
        uint64_t a = acc[rr >> 1];
        float y  = (rr & 1) ? hi32(a) : lo32(a);
        int  ia  = atom0 + (rr / 12);
        float p1 = g_P[(size_t)ia * 512 + c];
        float p2 = g_P[(size_t)s_idx[rr] * 512 + 256 + c];
        float g  = y + p1 + p2 + bc;
        g_gated[(size_t)(r0 + rr) * 256 + c] = g;
        float m = s_m[rr];
        sloc  = fmaf(m, g, sloc);
        ssloc = fmaf(m * g, g, ssloc);
    }
    atomicAdd(&g_stats1[c],       sloc);
    atomicAdd(&g_stats1[256 + c], ssloc);
    if (tid == 0) {
        float cl = 0.f;
        #pragma unroll
        for (int rr = 0; rr < 48; rr++) cl += s_m[rr];
        atomicAdd(&g_stats1[512], cl);
    }
}

// ---------------- kernel D: BN1 + sigmoid*softplus gate + sum_j, + BN2 stats ----
// 8 atoms per block, 128 threads = one output channel each.
__global__ void __launch_bounds__(128) kernelD(
    const float* __restrict__ mask,
    const float* __restrict__ gamma1, const float* __restrict__ beta1)
{
    const int c     = threadIdx.x;
    const int atom0 = blockIdx.x * 8;

    const float inv_cnt = 1.f / g_stats1[512];
    const float mf = g_stats1[c]       * inv_cnt;
    const float mc = g_stats1[c + 128] * inv_cnt;
    const float vf = g_stats1[256 + c]       * inv_cnt - mf * mf;
    const float vc = g_stats1[256 + c + 128] * inv_cnt - mc * mc;
    const float sf = rsqrtf(vf + BN_EPS) * gamma1[c];
    const float sc = rsqrtf(vc + BN_EPS) * gamma1[c + 128];
    const float bf = beta1[c];
    const float bcore = beta1[c + 128];

    float sloc = 0.f, ssloc = 0.f;
    for (int a = 0; a < 8; a++) {
        const int i = atom0 + a;
        float accv = 0.f;
        #pragma unroll
        for (int j = 0; j < 12; j++) {
            float m = mask[i * 12 + j];          // uniform across block
            if (m != 0.f) {                      // unmasked rows contribute exactly 0
                const float* gp = g_gated + (size_t)(i * 12 + j) * 256;
                float hf = (gp[c]       - mf) * sf + bf;
                float hc = (gp[c + 128] - mc) * sc + bcore;
                accv += sigmoidf_(hf) * softplusf_(hc);
            }
        }
        g_nbrsum[(size_t)i * 128 + c] = accv;
        sloc  += accv;
        ssloc += accv * accv;
    }
    atomicAdd(&g_stats2[c],       sloc);
    atomicAdd(&g_stats2[128 + c], ssloc);
}

// ---------------- kernel F: out = softplus(atom + BN2(nbrsum)) ----------------
__global__ void __launch_bounds__(256) kernelF(
    const float* __restrict__ atom,
    const float* __restrict__ gamma2, const float* __restrict__ beta2,
    float* __restrict__ out)
{
    int t = blockIdx.x * 256 + threadIdx.x;
    if (t >= N_ATOMS * 128) return;
    int c = t & 127;
    const float invN = 1.f / (float)N_ATOMS;
    float mean = g_stats2[c] * invN;
    float var  = g_stats2[128 + c] * invN - mean * mean;
    float x = (g_nbrsum[t] - mean) * rsqrtf(var + BN_EPS) * gamma2[c] + beta2[c];
    out[t] = softplusf_(atom[t] + x);
}

// ---------------- launch ----------------
extern "C" void kernel_launch(void* const* d_in, const int* in_sizes, int n_in,
                              void* d_out, int out_size)
{
    const float* atom   = (const float*)d_in[0];
    const float* nbr    = (const float*)d_in[1];
    const int*   idx    = (const int*)  d_in[2];
    const float* mask   = (const float*)d_in[3];
    const float* W      = (const float*)d_in[4];
    const float* bias   = (const float*)d_in[5];
    const float* gamma1 = (const float*)d_in[6];
    const float* beta1  = (const float*)d_in[7];
    const float* gamma2 = (const float*)d_in[8];
    const float* beta2  = (const float*)d_in[9];
    float* out = (float*)d_out;

    zero_stats_kernel<<<1, 1024>>>();
    gemmA_kernel<<<(N_ATOMS + 31) / 32, 256>>>(atom, W);
    kernelB<<<N_ATOMS / 4, 256>>>(nbr, idx, mask, W, bias);
    kernelD<<<N_ATOMS / 8, 128>>>(mask, gamma1, beta1);
    kernelF<<<(N_ATOMS * 128) / 256, 256>>>(atom, gamma2, beta2, out);
}

// round 2
// speedup vs baseline: 1.4279x; 1.4279x over previous
#include <cuda_runtime.h>
#include <cstdint>

#define N_ATOMS 50000
#define M_NBR   12
#define N_ROWS  (N_ATOMS * M_NBR)
#define BN_EPS  1e-5f

// ---------------- scratch (device globals; no allocation) ----------------
__device__ float g_P[(size_t)N_ATOMS * 512];       // [i][0:256)=atom@W1, [256:512)=atom@W2
__device__ float g_gated[(size_t)N_ROWS * 256];    // pre-BN gated features (active rows only)
__device__ float g_nbrsum[(size_t)N_ATOMS * 128];
__device__ float g_stats1[513];                    // S[256], SS[256], cnt
__device__ float g_stats2[256];                    // S2[128], SS2[128]
__device__ int   g_rows[N_ROWS];                   // compacted active row indices
__device__ int   g_nactive;

// ---------------- f32x2 helpers ----------------
__device__ __forceinline__ uint64_t pack2(float lo, float hi) {
    uint64_t r; asm("mov.b64 %0, {%1, %2};" : "=l"(r) : "f"(lo), "f"(hi)); return r;
}
__device__ __forceinline__ void fma2(uint64_t& d, uint64_t a, uint64_t b) {
    asm("fma.rn.f32x2 %0, %1, %2, %0;" : "+l"(d) : "l"(a), "l"(b));
}
__device__ __forceinline__ float lo32(uint64_t v) { return __uint_as_float((unsigned)(v & 0xffffffffu)); }
__device__ __forceinline__ float hi32(uint64_t v) { return __uint_as_float((unsigned)(v >> 32)); }

__device__ __forceinline__ float sigmoid_fast(float x) {
    float z = __expf(-fabsf(x));
    return __fdividef((x >= 0.f) ? 1.f : z, 1.f + z);
}
__device__ __forceinline__ float softplus_fast(float x) {
    return fmaxf(x, 0.f) + __logf(1.f + __expf(-fabsf(x)));
}

// ---------------- kernel 0: zero stats ----------------
__global__ void zero_stats_kernel() {
    int t = threadIdx.x;
    if (t < 513) g_stats1[t] = 0.f;
    if (t < 256) g_stats2[t] = 0.f;
    if (t == 0)  g_nactive = 0;
}

// ---------------- kernel C: compact active rows ----------------
__global__ void compact_kernel(const float* __restrict__ mask) {
    int t = blockIdx.x * 256 + threadIdx.x;
    bool in = (t < N_ROWS) && (mask[t] != 0.f);
    unsigned b = __ballot_sync(0xffffffffu, in);
    int lane = threadIdx.x & 31;
    int cnt = __popc(b);
    int base = 0;
    if (lane == 0 && cnt) {
        base = atomicAdd(&g_nactive, cnt);
        atomicAdd(&g_stats1[512], (float)cnt);
    }
    base = __shfl_sync(0xffffffffu, base, 0);
    if (in) g_rows[base + __popc(b & ((1u << lane) - 1u))] = t;
}

// ---------------- kernel A: P = atom @ [W1|W2]  (50000x128 @ 128x512) ----
// 32 rows x 512 cols per block, 256 threads. Thread: 8 rows (4 pairs) x 8 strided cols.
// W staged in smem in k-chunks of 16 (conflict-free LDS.32, no L1 wavefront storm).
__global__ void __launch_bounds__(256, 2) gemmA_kernel(
    const float* __restrict__ atom, const float* __restrict__ W)
{
    __shared__ float s_a[128 * 32];   // [k][r] transposed, 16KB
    __shared__ float s_w[16 * 512];   // chunk [kk][c], 32KB

    const int tid  = threadIdx.x;
    const int row0 = blockIdx.x * 32;

    // load A tile (zero-pad out-of-range rows)
    for (int t = tid; t < 1024; t += 256) {
        int r  = t & 31;
        int kq = t >> 5;
        float4 v = make_float4(0.f, 0.f, 0.f, 0.f);
        int gr = row0 + r;
        if (gr < N_ATOMS) v = *(const float4*)(atom + (size_t)gr * 128 + kq * 4);
        s_a[(kq * 4 + 0) * 32 + r] = v.x;
        s_a[(kq * 4 + 1) * 32 + r] = v.y;
        s_a[(kq * 4 + 2) * 32 + r] = v.z;
        s_a[(kq * 4 + 3) * 32 + r] = v.w;
    }

    const int cx = tid & 63;          // col lane: c = cx + 64*q
    const int ry = tid >> 6;          // 0..3 -> rows ry*8 .. ry*8+7 (4 pairs)

    uint64_t acc[4][8];
    #pragma unroll
    for (int p = 0; p < 4; p++)
        #pragma unroll
        for (int q = 0; q < 8; q++) acc[p][q] = 0ull;

    for (int chunk = 0; chunk < 8; chunk++) {
        const int k0 = chunk * 16;
        __syncthreads();
        // stage W chunk: 16 k x 512 cols (cols 0..255 from W1 rows, 256..511 from W2 rows)
        for (int t = tid; t < 2048; t += 256) {
            int kk = t >> 7;          // 0..15
            int c4 = (t & 127) * 4;   // 0..508
            const float* src = (c4 < 256)
                ? (W + (size_t)(k0 + kk) * 256 + c4)
                : (W + (size_t)(k0 + kk + 128) * 256 + (c4 - 256));
            *(float4*)(s_w + kk * 512 + c4) = *(const float4*)src;
        }
        __syncthreads();

        #pragma unroll 4
        for (int kk = 0; kk < 16; kk++) {
            const float* sa = s_a + (k0 + kk) * 32 + ry * 8;
            ulonglong2 a01 = *(const ulonglong2*)(sa);
            ulonglong2 a23 = *(const ulonglong2*)(sa + 4);
            uint64_t ap[4] = { a01.x, a01.y, a23.x, a23.y };
            const float* sw = s_w + kk * 512 + cx;
            uint64_t wp[8];
            #pragma unroll
            for (int q = 0; q < 8; q++) { float w = sw[64 * q]; wp[q] = pack2(w, w); }
            #pragma unroll
            for (int p = 0; p < 4; p++)
                #pragma unroll
                for (int q = 0; q < 8; q++)
                    fma2(acc[p][q], ap[p], wp[q]);
        }
    }

    #pragma unroll
    for (int p = 0; p < 4; p++) {
        int r_lo = row0 + ry * 8 + 2 * p;
        int r_hi = r_lo + 1;
        #pragma unroll
        for (int q = 0; q < 8; q++) {
            int c = cx + 64 * q;
            if (r_lo < N_ATOMS) g_P[(size_t)r_lo * 512 + c] = lo32(acc[p][q]);
            if (r_hi < N_ATOMS) g_P[(size_t)r_hi * 512 + c] = hi32(acc[p][q]);
        }
    }
}

// ---------------- kernel B: gated = nbr@W3 + P1 + P2[idx] + b (active rows only) ----
// 24 compacted rows per block, 256 threads = one output column each.
__global__ void __launch_bounds__(256, 2) kernelB(
    const float* __restrict__ nbr, const int* __restrict__ idx,
    const float* __restrict__ W, const float* __restrict__ bias)
{
    __shared__ float s_v[64 * 24];    // [k][r] transposed, pairs of rows adjacent
    __shared__ int   s_row[24];
    __shared__ int   s_atom[24];
    __shared__ int   s_idx[24];

    const int na = g_nactive;
    const int slot0 = blockIdx.x * 24;
    if (slot0 >= na) return;

    const int tid = threadIdx.x;

    if (tid < 24) {
        int slot = slot0 + tid;
        int gr = (slot < na) ? g_rows[slot] : -1;
        s_row[tid]  = gr;
        s_atom[tid] = (gr >= 0) ? (gr / 12) : 0;
        s_idx[tid]  = (gr >= 0) ? idx[gr] : 0;
    }
    __syncthreads();

    for (int t = tid; t < 24 * 16; t += 256) {    // 24 rows x 16 float4
        int r  = t % 24;
        int kq = t / 24;
        int gr = s_row[r];
        float4 v = make_float4(0.f, 0.f, 0.f, 0.f);
        if (gr >= 0) v = *(const float4*)(nbr + (size_t)gr * 64 + kq * 4);
        s_v[(kq * 4 + 0) * 24 + r] = v.x;
        s_v[(kq * 4 + 1) * 24 + r] = v.y;
        s_v[(kq * 4 + 2) * 24 + r] = v.z;
        s_v[(kq * 4 + 3) * 24 + r] = v.w;
    }
    __syncthreads();

    const int c = tid;
    const float* W3c = W + 256 * 256 + c;         // 64KB, L1-resident, coalesced per warp

    uint64_t acc[12];
    #pragma unroll
    for (int i = 0; i < 12; i++) acc[i] = 0ull;

    #pragma unroll 4
    for (int k = 0; k < 64; k++) {
        float w = __ldg(W3c + k * 256);
        uint64_t wp = pack2(w, w);
        const ulonglong2* vp = (const ulonglong2*)(s_v + k * 24);
        #pragma unroll
        for (int rq = 0; rq < 6; rq++) {
            ulonglong2 v2 = vp[rq];
            fma2(acc[2 * rq],     v2.x, wp);
            fma2(acc[2 * rq + 1], v2.y, wp);
        }
    }

    const float bc = bias[c];
    float sloc = 0.f, ssloc = 0.f;
    #pragma unroll 4
    for (int rr = 0; rr < 24; rr++) {
        int gr = s_row[rr];
        if (gr < 0) continue;
        uint64_t a = acc[rr >> 1];
        float y  = (rr & 1) ? hi32(a) : lo32(a);
        float p1 = g_P[(size_t)s_atom[rr] * 512 + c];
        float p2 = g_P[(size_t)s_idx[rr] * 512 + 256 + c];
        float g  = y + p1 + p2 + bc;
        g_gated[(size_t)gr * 256 + c] = g;
        sloc  += g;
        ssloc  = fmaf(g, g, ssloc);
    }
    atomicAdd(&g_stats1[c],       sloc);
    atomicAdd(&g_stats1[256 + c], ssloc);
}

// ---------------- kernel D: BN1 + sigmoid*softplus + sum_j, + BN2 stats ----
__global__ void __launch_bounds__(128) kernelD(
    const float* __restrict__ mask,
    const float* __restrict__ gamma1, const float* __restrict__ beta1)
{
    const int c     = threadIdx.x;
    const int atom0 = blockIdx.x * 8;

    const float inv_cnt = __fdividef(1.f, g_stats1[512]);
    const float mf = g_stats1[c]       * inv_cnt;
    const float mc = g_stats1[c + 128] * inv_cnt;
    const float vf = g_stats1[256 + c]       * inv_cnt - mf * mf;
    const float vc = g_stats1[256 + c + 128] * inv_cnt - mc * mc;
    const float sf = rsqrtf(vf + BN_EPS) * gamma1[c];
    const float sc = rsqrtf(vc + BN_EPS) * gamma1[c + 128];
    const float bf = beta1[c];
    const float bcr = beta1[c + 128];

    float sloc = 0.f, ssloc = 0.f;
    for (int a = 0; a < 8; a++) {
        const int i = atom0 + a;
        float accv = 0.f;
        #pragma unroll
        for (int j = 0; j < 12; j++) {
            float m = mask[i * 12 + j];
            if (m != 0.f) {
                const float* gp = g_gated + (size_t)(i * 12 + j) * 256;
                float hf = (gp[c]       - mf) * sf + bf;
                float hc = (gp[c + 128] - mc) * sc + bcr;
                accv += sigmoid_fast(hf) * softplus_fast(hc);
            }
        }
        g_nbrsum[(size_t)i * 128 + c] = accv;
        sloc  += accv;
        ssloc  = fmaf(accv, accv, ssloc);
    }
    atomicAdd(&g_stats2[c],       sloc);
    atomicAdd(&g_stats2[128 + c], ssloc);
}

// ---------------- kernel F: out = softplus(atom + BN2(nbrsum)) ----------------
__global__ void __launch_bounds__(256) kernelF(
    const float* __restrict__ atom,
    const float* __restrict__ gamma2, const float* __restrict__ beta2,
    float* __restrict__ out)
{
    int t = blockIdx.x * 256 + threadIdx.x;
    if (t >= N_ATOMS * 128) return;
    int c = t & 127;
    const float invN = 1.f / (float)N_ATOMS;
    float mean = g_stats2[c] * invN;
    float var  = g_stats2[128 + c] * invN - mean * mean;
    float x = (g_nbrsum[t] - mean) * rsqrtf(var + BN_EPS) * gamma2[c] + beta2[c];
    out[t] = softplus_fast(atom[t] + x);
}

// ---------------- launch ----------------
extern "C" void kernel_launch(void* const* d_in, const int* in_sizes, int n_in,
                              void* d_out, int out_size)
{
    const float* atom   = (const float*)d_in[0];
    const float* nbr    = (const float*)d_in[1];
    const int*   idx    = (const int*)  d_in[2];
    const float* mask   = (const float*)d_in[3];
    const float* W      = (const float*)d_in[4];
    const float* bias   = (const float*)d_in[5];
    const float* gamma1 = (const float*)d_in[6];
    const float* beta1  = (const float*)d_in[7];
    const float* gamma2 = (const float*)d_in[8];
    const float* beta2  = (const float*)d_in[9];
    float* out = (float*)d_out;

    zero_stats_kernel<<<1, 1024>>>();
    compact_kernel<<<(N_ROWS + 255) / 256, 256>>>(mask);
    gemmA_kernel<<<(N_ATOMS + 31) / 32, 256>>>(atom, W);
    kernelB<<<(N_ROWS + 23) / 24, 256>>>(nbr, idx, W, bias);
    kernelD<<<N_ATOMS / 8, 128>>>(mask, gamma1, beta1);
    kernelF<<<(N_ATOMS * 128) / 256, 256>>>(atom, gamma2, beta2, out);
}

// round 3
// speedup vs baseline: 1.8290x; 1.2809x over previous
#include <cuda_runtime.h>
#include <cstdint>

#define N_ATOMS 50000
#define M_NBR   12
#define N_ROWS  (N_ATOMS * M_NBR)
#define BN_EPS  1e-5f

// ---------------- scratch (device globals; no allocation) ----------------
__device__ float  g_P[(size_t)N_ATOMS * 512];       // [i][0:256)=atom@W1, [256:512)=atom@W2
__device__ float  g_gated[(size_t)N_ROWS * 256];    // pre-BN gated features (active rows only)
__device__ float  g_nbrsum[(size_t)N_ATOMS * 128];
__device__ float  g_stats1[513];                    // S[256], SS[256], cnt
__device__ float  g_stats2[256];                    // S2[128], SS2[128]
__device__ int    g_rows[N_ROWS];                   // compacted active row indices
__device__ int    g_nactive;
__device__ float2 g_W3dup[64 * 256];                // W3 prepacked as (w,w) pairs, 128KB

// ---------------- f32x2 helpers ----------------
__device__ __forceinline__ uint64_t pack2(float lo, float hi) {
    uint64_t r; asm("mov.b64 %0, {%1, %2};" : "=l"(r) : "f"(lo), "f"(hi)); return r;
}
__device__ __forceinline__ void fma2(uint64_t& d, uint64_t a, uint64_t b) {
    asm("fma.rn.f32x2 %0, %1, %2, %0;" : "+l"(d) : "l"(a), "l"(b));
}
__device__ __forceinline__ float lo32(uint64_t v) { return __uint_as_float((unsigned)(v & 0xffffffffu)); }
__device__ __forceinline__ float hi32(uint64_t v) { return __uint_as_float((unsigned)(v >> 32)); }

__device__ __forceinline__ float sigmoid_fast(float x) {
    float z = __expf(-fabsf(x));
    return __fdividef((x >= 0.f) ? 1.f : z, 1.f + z);
}
__device__ __forceinline__ float softplus_fast(float x) {
    return fmaxf(x, 0.f) + __logf(1.f + __expf(-fabsf(x)));
}

// ---------------- kernel 0: zero stats + prepack W3dup ----------------
__global__ void zero_stats_kernel() {
    int t = threadIdx.x;
    if (t < 513) g_stats1[t] = 0.f;
    if (t < 256) g_stats2[t] = 0.f;
    if (t == 0)  g_nactive = 0;
}

__global__ void prepack_kernel(const float* __restrict__ W) {
    int t = blockIdx.x * 256 + threadIdx.x;      // 0 .. 16383
    if (t < 64 * 256) {
        float w = W[256 * 256 + t];              // W3 rows start at k=256
        g_W3dup[t] = make_float2(w, w);
    }
}

// ---------------- kernel C: compact active rows ----------------
__global__ void compact_kernel(const float* __restrict__ mask) {
    int t = blockIdx.x * 256 + threadIdx.x;
    bool in = (t < N_ROWS) && (mask[t] != 0.f);
    unsigned b = __ballot_sync(0xffffffffu, in);
    int lane = threadIdx.x & 31;
    int cnt = __popc(b);
    int base = 0;
    if (lane == 0 && cnt) {
        base = atomicAdd(&g_nactive, cnt);
        atomicAdd(&g_stats1[512], (float)cnt);
    }
    base = __shfl_sync(0xffffffffu, base, 0);
    if (in) g_rows[base + __popc(b & ((1u << lane) - 1u))] = t;
}

// ---------------- kernel A: P = atom @ [W1|W2]  (50000x128 @ 128x512) ----
__global__ void __launch_bounds__(256, 2) gemmA_kernel(
    const float* __restrict__ atom, const float* __restrict__ W)
{
    __shared__ float s_a[128 * 32];   // [k][r] transposed, 16KB
    __shared__ float s_w[16 * 512];   // chunk [kk][c], 32KB

    const int tid  = threadIdx.x;
    const int row0 = blockIdx.x * 32;

    for (int t = tid; t < 1024; t += 256) {
        int r  = t & 31;
        int kq = t >> 5;
        float4 v = make_float4(0.f, 0.f, 0.f, 0.f);
        int gr = row0 + r;
        if (gr < N_ATOMS) v = *(const float4*)(atom + (size_t)gr * 128 + kq * 4);
        s_a[(kq * 4 + 0) * 32 + r] = v.x;
        s_a[(kq * 4 + 1) * 32 + r] = v.y;
        s_a[(kq * 4 + 2) * 32 + r] = v.z;
        s_a[(kq * 4 + 3) * 32 + r] = v.w;
    }

    const int cx = tid & 63;
    const int ry = tid >> 6;

    uint64_t acc[4][8];
    #pragma unroll
    for (int p = 0; p < 4; p++)
        #pragma unroll
        for (int q = 0; q < 8; q++) acc[p][q] = 0ull;

    for (int chunk = 0; chunk < 8; chunk++) {
        const int k0 = chunk * 16;
        __syncthreads();
        for (int t = tid; t < 2048; t += 256) {
            int kk = t >> 7;
            int c4 = (t & 127) * 4;
            const float* src = (c4 < 256)
                ? (W + (size_t)(k0 + kk) * 256 + c4)
                : (W + (size_t)(k0 + kk + 128) * 256 + (c4 - 256));
            *(float4*)(s_w + kk * 512 + c4) = *(const float4*)src;
        }
        __syncthreads();

        #pragma unroll 4
        for (int kk = 0; kk < 16; kk++) {
            const float* sa = s_a + (k0 + kk) * 32 + ry * 8;
            ulonglong2 a01 = *(const ulonglong2*)(sa);
            ulonglong2 a23 = *(const ulonglong2*)(sa + 4);
            uint64_t ap[4] = { a01.x, a01.y, a23.x, a23.y };
            const float* sw = s_w + kk * 512 + cx;
            uint64_t wp[8];
            #pragma unroll
            for (int q = 0; q < 8; q++) { float w = sw[64 * q]; wp[q] = pack2(w, w); }
            #pragma unroll
            for (int p = 0; p < 4; p++)
                #pragma unroll
                for (int q = 0; q < 8; q++)
                    fma2(acc[p][q], ap[p], wp[q]);
        }
    }

    #pragma unroll
    for (int p = 0; p < 4; p++) {
        int r_lo = row0 + ry * 8 + 2 * p;
        int r_hi = r_lo + 1;
        #pragma unroll
        for (int q = 0; q < 8; q++) {
            int c = cx + 64 * q;
            if (r_lo < N_ATOMS) g_P[(size_t)r_lo * 512 + c] = lo32(acc[p][q]);
            if (r_hi < N_ATOMS) g_P[(size_t)r_hi * 512 + c] = hi32(acc[p][q]);
        }
    }
}

// ---------------- kernel B: gated = nbr@W3 + P1 + P2[idx] + b (active rows only) ----
// 24 compacted rows per block, 256 threads = one output column each.
// Inner loop: LDG.64 of prepacked (w,w) + 6x LDS.128 broadcast + 12x fma2.
__global__ void __launch_bounds__(256, 3) kernelB(
    const float* __restrict__ nbr, const int* __restrict__ idx,
    const float* __restrict__ bias)
{
    __shared__ float s_v[64 * 24];    // [k][r] transposed; adjacent rows = f32x2 pair
    __shared__ int   s_row[24];
    __shared__ int   s_atom[24];
    __shared__ int   s_idx[24];

    const int na    = g_nactive;
    const int slot0 = blockIdx.x * 24;
    if (slot0 >= na) return;

    const int tid = threadIdx.x;

    if (tid < 24) {
        int slot = slot0 + tid;
        int gr = (slot < na) ? g_rows[slot] : -1;
        s_row[tid]  = gr;
        s_atom[tid] = (gr >= 0) ? (gr / 12) : 0;
        s_idx[tid]  = (gr >= 0) ? idx[gr] : 0;
    }
    __syncthreads();

    for (int t = tid; t < 24 * 16; t += 256) {
        int r  = t % 24;
        int kq = t / 24;
        int gr = s_row[r];
        float4 v = make_float4(0.f, 0.f, 0.f, 0.f);
        if (gr >= 0) v = *(const float4*)(nbr + (size_t)gr * 64 + kq * 4);
        s_v[(kq * 4 + 0) * 24 + r] = v.x;
        s_v[(kq * 4 + 1) * 24 + r] = v.y;
        s_v[(kq * 4 + 2) * 24 + r] = v.z;
        s_v[(kq * 4 + 3) * 24 + r] = v.w;
    }
    __syncthreads();

    const int c = tid;
    const uint64_t* __restrict__ Wd = (const uint64_t*)g_W3dup + c;   // stride 256 u64

    uint64_t acc[12];
    #pragma unroll
    for (int i = 0; i < 12; i++) acc[i] = 0ull;

    uint64_t wn = Wd[0];                      // prefetch k=0
    #pragma unroll 2
    for (int k = 0; k < 64; k++) {
        uint64_t w = wn;
        if (k < 63) wn = Wd[(k + 1) * 256];   // single-slot software pipeline
        const ulonglong2* vp = (const ulonglong2*)(s_v + k * 24);
        #pragma unroll
        for (int q = 0; q < 6; q++) {
            ulonglong2 v2 = vp[q];
            fma2(acc[2 * q],     v2.x, w);
            fma2(acc[2 * q + 1], v2.y, w);
        }
    }

    const float bc = bias[c];
    float sloc = 0.f, ssloc = 0.f;
    #pragma unroll 4
    for (int rr = 0; rr < 24; rr++) {
        int gr = s_row[rr];
        if (gr < 0) continue;
        uint64_t a = acc[rr >> 1];
        float y  = (rr & 1) ? hi32(a) : lo32(a);
        float p1 = g_P[(size_t)s_atom[rr] * 512 + c];
        float p2 = g_P[(size_t)s_idx[rr] * 512 + 256 + c];
        float g  = y + p1 + p2 + bc;
        g_gated[(size_t)gr * 256 + c] = g;
        sloc  += g;
        ssloc  = fmaf(g, g, ssloc);
    }
    atomicAdd(&g_stats1[c],       sloc);
    atomicAdd(&g_stats1[256 + c], ssloc);
}

// ---------------- kernel D: BN1 + sigmoid*softplus + sum_j, + BN2 stats ----
__global__ void __launch_bounds__(128) kernelD(
    const float* __restrict__ mask,
    const float* __restrict__ gamma1, const float* __restrict__ beta1)
{
    const int c     = threadIdx.x;
    const int atom0 = blockIdx.x * 8;

    const float inv_cnt = __fdividef(1.f, g_stats1[512]);
    const float mf = g_stats1[c]       * inv_cnt;
    const float mc = g_stats1[c + 128] * inv_cnt;
    const float vf = g_stats1[256 + c]       * inv_cnt - mf * mf;
    const float vc = g_stats1[256 + c + 128] * inv_cnt - mc * mc;
    const float sf = rsqrtf(vf + BN_EPS) * gamma1[c];
    const float sc = rsqrtf(vc + BN_EPS) * gamma1[c + 128];
    const float bf = beta1[c];
    const float bcr = beta1[c + 128];

    float sloc = 0.f, ssloc = 0.f;
    for (int a = 0; a < 8; a++) {
        const int i = atom0 + a;
        float accv = 0.f;
        #pragma unroll
        for (int j = 0; j < 12; j++) {
            float m = mask[i * 12 + j];
            if (m != 0.f) {
                const float* gp = g_gated + (size_t)(i * 12 + j) * 256;
                float hf = (gp[c]       - mf) * sf + bf;
                float hc = (gp[c + 128] - mc) * sc + bcr;
                accv += sigmoid_fast(hf) * softplus_fast(hc);
            }
        }
        g_nbrsum[(size_t)i * 128 + c] = accv;
        sloc  += accv;
        ssloc  = fmaf(accv, accv, ssloc);
    }
    atomicAdd(&g_stats2[c],       sloc);
    atomicAdd(&g_stats2[128 + c], ssloc);
}

// ---------------- kernel F: out = softplus(atom + BN2(nbrsum)) ----------------
__global__ void __launch_bounds__(256) kernelF(
    const float* __restrict__ atom,
    const float* __restrict__ gamma2, const float* __restrict__ beta2,
    float* __restrict__ out)
{
    int t = blockIdx.x * 256 + threadIdx.x;
    if (t >= N_ATOMS * 128) return;
    int c = t & 127;
    const float invN = 1.f / (float)N_ATOMS;
    float mean = g_stats2[c] * invN;
    float var  = g_stats2[128 + c] * invN - mean * mean;
    float x = (g_nbrsum[t] - mean) * rsqrtf(var + BN_EPS) * gamma2[c] + beta2[c];
    out[t] = softplus_fast(atom[t] + x);
}

// ---------------- launch ----------------
extern "C" void kernel_launch(void* const* d_in, const int* in_sizes, int n_in,
                              void* d_out, int out_size)
{
    const float* atom   = (const float*)d_in[0];
    const float* nbr    = (const float*)d_in[1];
    const int*   idx    = (const int*)  d_in[2];
    const float* mask   = (const float*)d_in[3];
    const float* W      = (const float*)d_in[4];
    const float* bias   = (const float*)d_in[5];
    const float* gamma1 = (const float*)d_in[6];
    const float* beta1  = (const float*)d_in[7];
    const float* gamma2 = (const float*)d_in[8];
    const float* beta2  = (const float*)d_in[9];
    float* out = (float*)d_out;

    zero_stats_kernel<<<1, 1024>>>();
    prepack_kernel<<<64, 256>>>(W);
    compact_kernel<<<(N_ROWS + 255) / 256, 256>>>(mask);
    gemmA_kernel<<<(N_ATOMS + 31) / 32, 256>>>(atom, W);
    kernelB<<<N_ROWS / 24, 256>>>(nbr, idx, bias);
    kernelD<<<N_ATOMS / 8, 128>>>(mask, gamma1, beta1);
    kernelF<<<(N_ATOMS * 128) / 256, 256>>>(atom, gamma2, beta2, out);
}